// round 2
// baseline (speedup 1.0000x reference)
#include <cuda_runtime.h>
#include <math.h>
#include <stdint.h>

#define B_    2
#define S_    2048
#define DM    1024
#define H_    16
#define DK    64
#define TOPK_ 16

// Scratch (allocation-free rule: __device__ globals)
__device__ float g_Q[B_ * S_ * DM];
__device__ float g_K[B_ * S_ * DM];
__device__ float g_V[B_ * S_ * DM];
__device__ float g_attn[B_ * S_ * DM];

// ---------------------------------------------------------------------------
// GEMM: C[M,N] = A[M,K] @ W[N,K]^T + bias[N]
// 64x64 tile, K-tile 16, 256 threads, 4x4 microtile per thread.
// ---------------------------------------------------------------------------
__global__ __launch_bounds__(256) void gemm_nt_bias(
    const float* __restrict__ A, const float* __restrict__ W,
    const float* __restrict__ bias, float* __restrict__ C,
    int M, int N, int K)
{
    __shared__ float As[16][68];   // [k][m]
    __shared__ float Ws[16][68];   // [k][n]

    const int bm = blockIdx.y * 64;
    const int bn = blockIdx.x * 64;
    const int tid = threadIdx.x;
    const int tx = tid & 15;       // n direction (16)
    const int ty = tid >> 4;       // m direction (16)

    const int lr = tid >> 2;       // row within tile (0..63)
    const int lc4 = tid & 3;       // which float4 along k (0..3)

    float acc[4][4];
#pragma unroll
    for (int i = 0; i < 4; i++)
#pragma unroll
        for (int j = 0; j < 4; j++) acc[i][j] = 0.f;

    for (int k0 = 0; k0 < K; k0 += 16) {
        float4 av = *(const float4*)(A + (size_t)(bm + lr) * K + k0 + lc4 * 4);
        float4 wv = *(const float4*)(W + (size_t)(bn + lr) * K + k0 + lc4 * 4);
        As[lc4 * 4 + 0][lr] = av.x; As[lc4 * 4 + 1][lr] = av.y;
        As[lc4 * 4 + 2][lr] = av.z; As[lc4 * 4 + 3][lr] = av.w;
        Ws[lc4 * 4 + 0][lr] = wv.x; Ws[lc4 * 4 + 1][lr] = wv.y;
        Ws[lc4 * 4 + 2][lr] = wv.z; Ws[lc4 * 4 + 3][lr] = wv.w;
        __syncthreads();

#pragma unroll
        for (int kk = 0; kk < 16; kk++) {
            float a[4], w[4];
#pragma unroll
            for (int i = 0; i < 4; i++) a[i] = As[kk][ty * 4 + i];
#pragma unroll
            for (int j = 0; j < 4; j++) w[j] = Ws[kk][tx * 4 + j];
#pragma unroll
            for (int i = 0; i < 4; i++)
#pragma unroll
                for (int j = 0; j < 4; j++) acc[i][j] += a[i] * w[j];
        }
        __syncthreads();
    }

#pragma unroll
    for (int i = 0; i < 4; i++) {
        float4 o;
        o.x = acc[i][0] + bias[bn + tx * 4 + 0];
        o.y = acc[i][1] + bias[bn + tx * 4 + 1];
        o.z = acc[i][2] + bias[bn + tx * 4 + 2];
        o.w = acc[i][3] + bias[bn + tx * 4 + 3];
        *(float4*)(C + (size_t)(bm + ty * 4 + i) * N + bn + tx * 4) = o;
    }
}

// ---------------------------------------------------------------------------
// Zero-fill (weights region)
// ---------------------------------------------------------------------------
__global__ __launch_bounds__(256) void zero_kernel(float4* __restrict__ p, size_t n4)
{
    size_t i = (size_t)blockIdx.x * blockDim.x + threadIdx.x;
    size_t stride = (size_t)gridDim.x * blockDim.x;
    float4 z = make_float4(0.f, 0.f, 0.f, 0.f);
    for (; i < n4; i += stride) p[i] = z;
}

// ---------------------------------------------------------------------------
// Fused scores -> top-16 -> softmax -> weights scatter -> attn = w @ V
// Block: 256 threads (8 warps) handles 8 queries of one (b,h).
// Smem: scores [8][2048], Qs [8][64], Ks [64][65]
// ---------------------------------------------------------------------------
__global__ __launch_bounds__(256) void attn_topk_kernel(
    const float* __restrict__ Q, const float* __restrict__ K,
    const float* __restrict__ V, float* __restrict__ weights,
    float* __restrict__ attn)
{
    extern __shared__ float sm[];
    float* sc = sm;                          // 8 * 2048
    float* Qs = sm + 8 * S_;                 // 8 * 64
    float* Ks = Qs + 8 * DK;                 // 64 * 65

    const int b = blockIdx.z;
    const int h = blockIdx.y;
    const int q0 = blockIdx.x * 8;
    const int tid = threadIdx.x;
    const int lane = tid & 31;
    const int wq = tid >> 5;                 // warp id == local query id

    // load Q tile (8 rows x 64 dims = 128 float4, threads 0..127)
    if (tid < 128) {
        int q = tid >> 4, c4 = tid & 15;
        float4 v = *(const float4*)(Q + (size_t)(b * S_ + q0 + q) * DM + h * DK + c4 * 4);
        float* dst = Qs + q * DK + c4 * 4;
        dst[0] = v.x; dst[1] = v.y; dst[2] = v.z; dst[3] = v.w;
    }
    __syncthreads();

    // cache this warp's query row in registers (reused over all 32 K tiles)
    float qreg[DK];
#pragma unroll
    for (int d = 0; d < DK; d++) qreg[d] = Qs[wq * DK + d];

    // scores: loop over 32 key tiles of 64
    for (int k0 = 0; k0 < S_; k0 += 64) {
        __syncthreads();
        // load K tile: 64 keys x 64 dims = 1024 float4 -> 4 per thread
#pragma unroll
        for (int r = 0; r < 4; r++) {
            int idx = tid + r * 256;         // 0..1023
            int key = idx >> 4;              // 0..63
            int c4 = idx & 15;               // 0..15
            float4 v = *(const float4*)(K + (size_t)(b * S_ + k0 + key) * DM + h * DK + c4 * 4);
            float* dst = Ks + key * 65 + c4 * 4;
            dst[0] = v.x; dst[1] = v.y; dst[2] = v.z; dst[3] = v.w;
        }
        __syncthreads();

        float acc0 = 0.f, acc1 = 0.f;
        const float* k1 = Ks + lane * 65;
        const float* k2 = Ks + (lane + 32) * 65;
#pragma unroll
        for (int d = 0; d < DK; d++) {
            float qv = qreg[d];
            acc0 += qv * k1[d];
            acc1 += qv * k2[d];
        }
        sc[wq * S_ + k0 + lane]      = acc0 * 0.125f;   // 1/sqrt(64)
        sc[wq * S_ + k0 + lane + 32] = acc1 * 0.125f;
    }
    __syncthreads();

    // top-16 per query (one warp per query), tie -> smaller index (matches lax.top_k)
    float* row = sc + wq * S_;
    float topv[TOPK_];
    int   topi[TOPK_];
#pragma unroll
    for (int t = 0; t < TOPK_; t++) {
        float bv = -INFINITY;
        int   bi = 0x7fffffff;
        for (int j = 0; j < S_ / 32; j++) {
            int idx = lane + (j << 5);
            float v = row[idx];
            if (v > bv) { bv = v; bi = idx; }
        }
#pragma unroll
        for (int off = 16; off > 0; off >>= 1) {
            float ov = __shfl_xor_sync(0xffffffffu, bv, off);
            int   oi = __shfl_xor_sync(0xffffffffu, bi, off);
            if (ov > bv || (ov == bv && oi < bi)) { bv = ov; bi = oi; }
        }
        topv[t] = bv; topi[t] = bi;
        if (lane == 0) row[bi] = -INFINITY;
        __syncwarp();
    }

    // softmax over the 16 survivors (topv[0] is the row max)
    const float m = topv[0];
    float sum = 0.f;
#pragma unroll
    for (int t = 0; t < TOPK_; t++) { topv[t] = __expf(topv[t] - m); sum += topv[t]; }
    const float inv = 1.f / sum;

    const int q = q0 + wq;
    float* wrow = weights + ((size_t)((b * H_ + h) * S_) + q) * S_;
    if (lane < TOPK_) wrow[topi[lane]] = topv[lane] * inv;

    // attn[b,q,h,:] = sum_j w_j * V[b, k_j, h, :]
    float a0 = 0.f, a1 = 0.f;
#pragma unroll
    for (int t = 0; t < TOPK_; t++) {
        const float* vrow = V + (size_t)(b * S_ + topi[t]) * DM + h * DK;
        float wgt = topv[t] * inv;
        a0 += wgt * vrow[lane];
        a1 += wgt * vrow[lane + 32];
    }
    float* arow = attn + (size_t)(b * S_ + q) * DM + h * DK;
    arow[lane]      = a0;
    arow[lane + 32] = a1;
}

// ---------------------------------------------------------------------------
extern "C" void kernel_launch(void* const* d_in, const int* in_sizes, int n_in,
                              void* d_out, int out_size)
{
    const float* query = (const float*)d_in[0];
    const float* key   = (const float*)d_in[1];
    const float* value = (const float*)d_in[2];
    const float* Wq = (const float*)d_in[3];
    const float* bq = (const float*)d_in[4];
    const float* Wk = (const float*)d_in[5];
    const float* bk = (const float*)d_in[6];
    const float* Wv = (const float*)d_in[7];
    const float* bv = (const float*)d_in[8];
    const float* Wo = (const float*)d_in[9];
    const float* bo = (const float*)d_in[10];

    float* out = (float*)d_out;
    float* weights = out + (size_t)B_ * S_ * DM;   // out first, then weights

    float *Qp, *Kp, *Vp, *Ap;
    cudaGetSymbolAddress((void**)&Qp, g_Q);
    cudaGetSymbolAddress((void**)&Kp, g_K);
    cudaGetSymbolAddress((void**)&Vp, g_V);
    cudaGetSymbolAddress((void**)&Ap, g_attn);

    const int M = B_ * S_;   // 4096
    const int N = DM, Kd = DM;
    dim3 gemm_grid(N / 64, M / 64);

    // zero the weights output region (16-sparse softmax -> rest is exactly 0)
    size_t n4 = (size_t)B_ * H_ * S_ * S_ / 4;
    zero_kernel<<<8192, 256>>>((float4*)weights, n4);

    // projections
    gemm_nt_bias<<<gemm_grid, 256>>>(query, Wq, bq, Qp, M, N, Kd);
    gemm_nt_bias<<<gemm_grid, 256>>>(key,   Wk, bk, Kp, M, N, Kd);
    gemm_nt_bias<<<gemm_grid, 256>>>(value, Wv, bv, Vp, M, N, Kd);

    // fused scores -> top-k -> softmax -> scatter -> attn
    size_t smem = (size_t)(8 * S_ + 8 * DK + 64 * 65) * sizeof(float);  // ~84 KB
    cudaFuncSetAttribute(attn_topk_kernel,
                         cudaFuncAttributeMaxDynamicSharedMemorySize, (int)smem);
    dim3 attn_grid(S_ / 8, H_, B_);
    attn_topk_kernel<<<attn_grid, 256, smem>>>(Qp, Kp, Vp, weights, Ap);

    // output projection
    gemm_nt_bias<<<gemm_grid, 256>>>(Ap, Wo, bo, out, M, N, Kd);
}

// round 3
// speedup vs baseline: 1.4734x; 1.4734x over previous
#include <cuda_runtime.h>
#include <math.h>
#include <stdint.h>

#define B_    2
#define S_    2048
#define DM    1024
#define H_    16
#define DK    64
#define TOPK_ 16

// Scratch (allocation-free rule: __device__ globals)
__device__ float g_Q[B_ * S_ * DM];
__device__ float g_K[B_ * S_ * DM];
__device__ float g_V[B_ * S_ * DM];
__device__ float g_attn[B_ * S_ * DM];

// ---------------------------------------------------------------------------
// GEMM: C[M,N] = A[M,K] @ W[N,K]^T + bias[N]
// 128x128 tile, K-tile 16, 256 threads, 8x8 microtile -> 16 FFMA per LDS.128
// ---------------------------------------------------------------------------
__global__ __launch_bounds__(256, 2) void gemm_nt_bias(
    const float* __restrict__ A, const float* __restrict__ W,
    const float* __restrict__ bias, float* __restrict__ C,
    int M, int N, int K)
{
    __shared__ float As[16][132];   // [k][m]
    __shared__ float Ws[16][132];   // [k][n]

    const int bm = blockIdx.y * 128;
    const int bn = blockIdx.x * 128;
    const int tid = threadIdx.x;
    const int tx = tid & 15;        // n dir
    const int ty = tid >> 4;        // m dir

    float acc[8][8];
#pragma unroll
    for (int i = 0; i < 8; i++)
#pragma unroll
        for (int j = 0; j < 8; j++) acc[i][j] = 0.f;

    for (int k0 = 0; k0 < K; k0 += 16) {
        // load 128x16 A tile and W tile: 512 float4 each -> 2 per thread
#pragma unroll
        for (int r = 0; r < 2; r++) {
            int idx = tid + r * 256;       // 0..511
            int row = idx >> 2;            // 0..127
            int c4  = idx & 3;             // 0..3
            float4 av = *(const float4*)(A + (size_t)(bm + row) * K + k0 + c4 * 4);
            float4 wv = *(const float4*)(W + (size_t)(bn + row) * K + k0 + c4 * 4);
            As[c4 * 4 + 0][row] = av.x; As[c4 * 4 + 1][row] = av.y;
            As[c4 * 4 + 2][row] = av.z; As[c4 * 4 + 3][row] = av.w;
            Ws[c4 * 4 + 0][row] = wv.x; Ws[c4 * 4 + 1][row] = wv.y;
            Ws[c4 * 4 + 2][row] = wv.z; Ws[c4 * 4 + 3][row] = wv.w;
        }
        __syncthreads();

#pragma unroll
        for (int kk = 0; kk < 16; kk++) {
            float4 a0 = *(const float4*)&As[kk][ty * 8];
            float4 a1 = *(const float4*)&As[kk][ty * 8 + 4];
            float4 b0 = *(const float4*)&Ws[kk][tx * 8];
            float4 b1 = *(const float4*)&Ws[kk][tx * 8 + 4];
            float a[8] = {a0.x, a0.y, a0.z, a0.w, a1.x, a1.y, a1.z, a1.w};
            float b[8] = {b0.x, b0.y, b0.z, b0.w, b1.x, b1.y, b1.z, b1.w};
#pragma unroll
            for (int i = 0; i < 8; i++)
#pragma unroll
                for (int j = 0; j < 8; j++) acc[i][j] += a[i] * b[j];
        }
        __syncthreads();
    }

#pragma unroll
    for (int i = 0; i < 8; i++) {
        float* crow = C + (size_t)(bm + ty * 8 + i) * N + bn + tx * 8;
#pragma unroll
        for (int j4 = 0; j4 < 2; j4++) {
            float4 o;
            o.x = acc[i][j4 * 4 + 0] + bias[bn + tx * 8 + j4 * 4 + 0];
            o.y = acc[i][j4 * 4 + 1] + bias[bn + tx * 8 + j4 * 4 + 1];
            o.z = acc[i][j4 * 4 + 2] + bias[bn + tx * 8 + j4 * 4 + 2];
            o.w = acc[i][j4 * 4 + 3] + bias[bn + tx * 8 + j4 * 4 + 3];
            *(float4*)(crow + j4 * 4) = o;
        }
    }
}

// ---------------------------------------------------------------------------
// Zero-fill (weights region)
// ---------------------------------------------------------------------------
__global__ __launch_bounds__(256) void zero_kernel(float4* __restrict__ p, size_t n4)
{
    size_t i = (size_t)blockIdx.x * blockDim.x + threadIdx.x;
    size_t stride = (size_t)gridDim.x * blockDim.x;
    float4 z = make_float4(0.f, 0.f, 0.f, 0.f);
    for (; i < n4; i += stride) p[i] = z;
}

// ---------------------------------------------------------------------------
// Sorted top-16 insertion. Lanes 0..15 hold (v,i) sorted desc (v[15] = min).
// Caller guarantees cv > current min. Candidates arrive in ascending index
// order; strict '>' keep-test preserves lax.top_k tie ordering.
// ---------------------------------------------------------------------------
__device__ __forceinline__ void insert16(float& v, int& i, float cv, int cidx, int lane)
{
    unsigned keep = __ballot_sync(0xffffffffu,
        (lane < 16) && (v > cv || (v == cv && i < cidx)));
    int pos = __popc(keep & 0xffffu);
    float vu = __shfl_up_sync(0xffffffffu, v, 1);
    int   iu = __shfl_up_sync(0xffffffffu, i, 1);
    if (lane < 16) {
        if (lane == pos)      { v = cv; i = cidx; }
        else if (lane > pos)  { v = vu; i = iu;  }
    }
}

// ---------------------------------------------------------------------------
// Fused scores -> streaming top-16 -> softmax -> weights scatter -> attn=w@V
// Block: 256 threads, 64 queries of one (b,h). Score tiles are a register-
// tiled 64x64x64 GEMM; top-16 kept in registers across the key stream.
// smem: Qs[64][68] (d-major), Ks[64][68] (d-major), Sc[64][68] (q-major)
// ---------------------------------------------------------------------------
__global__ __launch_bounds__(256) void attn_topk_kernel(
    const float* __restrict__ Q, const float* __restrict__ K,
    const float* __restrict__ V, float* __restrict__ weights,
    float* __restrict__ attn)
{
    extern __shared__ float sm[];
    float* Qs = sm;                        // 64*68  [d][q]
    float* Ks = Qs + 64 * 68;              // 64*68  [d][key]
    float* Sc = Ks + 64 * 68;              // 64*68  [q][key]

    const int b = blockIdx.z;
    const int h = blockIdx.y;
    const int q0 = blockIdx.x * 64;
    const int tid = threadIdx.x;
    const int lane = tid & 31;
    const int wid = tid >> 5;              // 8 warps
    const int tx = tid & 15;
    const int ty = tid >> 4;

    // load Q tile transposed: [d][q]
#pragma unroll
    for (int r = 0; r < 4; r++) {
        int idx = tid + r * 256;           // 0..1023
        int q = idx >> 4, c4 = idx & 15;
        float4 v = *(const float4*)(Q + (size_t)(b * S_ + q0 + q) * DM + h * DK + c4 * 4);
        Qs[(c4 * 4 + 0) * 68 + q] = v.x;
        Qs[(c4 * 4 + 1) * 68 + q] = v.y;
        Qs[(c4 * 4 + 2) * 68 + q] = v.z;
        Qs[(c4 * 4 + 3) * 68 + q] = v.w;
    }

    // top-16 state: warp owns queries wid*8 .. wid*8+7; lanes 0..15 sorted desc
    float tv[8];
    int   ti[8];
#pragma unroll
    for (int j = 0; j < 8; j++) { tv[j] = -INFINITY; ti[j] = 0x7fffffff; }

    for (int k0 = 0; k0 < S_; k0 += 64) {
        __syncthreads();
        // load K tile transposed: [d][key]
#pragma unroll
        for (int r = 0; r < 4; r++) {
            int idx = tid + r * 256;
            int key = idx >> 4, c4 = idx & 15;
            float4 v = *(const float4*)(K + (size_t)(b * S_ + k0 + key) * DM + h * DK + c4 * 4);
            Ks[(c4 * 4 + 0) * 68 + key] = v.x;
            Ks[(c4 * 4 + 1) * 68 + key] = v.y;
            Ks[(c4 * 4 + 2) * 68 + key] = v.z;
            Ks[(c4 * 4 + 3) * 68 + key] = v.w;
        }
        __syncthreads();

        // 64x64 score tile: 4x4 microtile
        float acc[4][4];
#pragma unroll
        for (int i = 0; i < 4; i++)
#pragma unroll
            for (int j = 0; j < 4; j++) acc[i][j] = 0.f;

#pragma unroll 16
        for (int kk = 0; kk < 64; kk++) {
            float4 a4 = *(const float4*)&Qs[kk * 68 + ty * 4];
            float4 b4 = *(const float4*)&Ks[kk * 68 + tx * 4];
            float a[4] = {a4.x, a4.y, a4.z, a4.w};
            float bb[4] = {b4.x, b4.y, b4.z, b4.w};
#pragma unroll
            for (int i = 0; i < 4; i++)
#pragma unroll
                for (int j = 0; j < 4; j++) acc[i][j] += a[i] * bb[j];
        }
#pragma unroll
        for (int i = 0; i < 4; i++) {
            float4 o;
            o.x = acc[i][0] * 0.125f; o.y = acc[i][1] * 0.125f;
            o.z = acc[i][2] * 0.125f; o.w = acc[i][3] * 0.125f;
            *(float4*)&Sc[(ty * 4 + i) * 68 + tx * 4] = o;
        }
        __syncthreads();

        // streaming top-16 update: warp handles its 8 queries
#pragma unroll
        for (int j = 0; j < 8; j++) {
            int q = wid * 8 + j;
            float s0 = Sc[q * 68 + lane];
            float s1 = Sc[q * 68 + 32 + lane];
            float thr = __shfl_sync(0xffffffffu, tv[j], 15);

            unsigned m0 = __ballot_sync(0xffffffffu, s0 > thr);
            while (m0) {
                int src = __ffs(m0) - 1; m0 &= m0 - 1;
                float cv = __shfl_sync(0xffffffffu, s0, src);
                float curmin = __shfl_sync(0xffffffffu, tv[j], 15);
                if (cv > curmin) insert16(tv[j], ti[j], cv, k0 + src, lane);
            }
            unsigned m1 = __ballot_sync(0xffffffffu, s1 > thr);
            while (m1) {
                int src = __ffs(m1) - 1; m1 &= m1 - 1;
                float cv = __shfl_sync(0xffffffffu, s1, src);
                float curmin = __shfl_sync(0xffffffffu, tv[j], 15);
                if (cv > curmin) insert16(tv[j], ti[j], cv, k0 + 32 + src, lane);
            }
        }
    }

    // softmax over 16 survivors + scatter + attn = w @ V
#pragma unroll
    for (int j = 0; j < 8; j++) {
        const int q = q0 + wid * 8 + j;
        float m = __shfl_sync(0xffffffffu, tv[j], 0);       // max
        float e = (lane < 16) ? __expf(tv[j] - m) : 0.f;
        float s = e;
#pragma unroll
        for (int off = 8; off > 0; off >>= 1)
            s += __shfl_xor_sync(0xffffffffu, s, off);       // lanes 0..15 -> sum
        s = __shfl_sync(0xffffffffu, s, 0);
        float w = e / s;                                     // valid on lanes 0..15

        float* wrow = weights + ((size_t)((b * H_ + h) * S_) + q) * S_;
        if (lane < 16) wrow[ti[j]] = w;

        float a0 = 0.f, a1 = 0.f;
#pragma unroll
        for (int t = 0; t < TOPK_; t++) {
            float wt = __shfl_sync(0xffffffffu, w, t);
            int  idx = __shfl_sync(0xffffffffu, ti[j], t);
            const float* vr = V + (size_t)(b * S_ + idx) * DM + h * DK;
            a0 += wt * vr[lane];
            a1 += wt * vr[lane + 32];
        }
        float* arow = attn + (size_t)(b * S_ + q) * DM + h * DK;
        arow[lane]      = a0;
        arow[lane + 32] = a1;
    }
}

// ---------------------------------------------------------------------------
extern "C" void kernel_launch(void* const* d_in, const int* in_sizes, int n_in,
                              void* d_out, int out_size)
{
    const float* query = (const float*)d_in[0];
    const float* key   = (const float*)d_in[1];
    const float* value = (const float*)d_in[2];
    const float* Wq = (const float*)d_in[3];
    const float* bq = (const float*)d_in[4];
    const float* Wk = (const float*)d_in[5];
    const float* bk = (const float*)d_in[6];
    const float* Wv = (const float*)d_in[7];
    const float* bv = (const float*)d_in[8];
    const float* Wo = (const float*)d_in[9];
    const float* bo = (const float*)d_in[10];

    float* out = (float*)d_out;
    float* weights = out + (size_t)B_ * S_ * DM;

    float *Qp, *Kp, *Vp, *Ap;
    cudaGetSymbolAddress((void**)&Qp, g_Q);
    cudaGetSymbolAddress((void**)&Kp, g_K);
    cudaGetSymbolAddress((void**)&Vp, g_V);
    cudaGetSymbolAddress((void**)&Ap, g_attn);

    const int M = B_ * S_;   // 4096
    const int N = DM, Kd = DM;
    dim3 gemm_grid(N / 128, M / 128);     // (8, 32)

    // zero the weights output region
    size_t n4 = (size_t)B_ * H_ * S_ * S_ / 4;
    zero_kernel<<<8192, 256>>>((float4*)weights, n4);

    // projections
    gemm_nt_bias<<<gemm_grid, 256>>>(query, Wq, bq, Qp, M, N, Kd);
    gemm_nt_bias<<<gemm_grid, 256>>>(key,   Wk, bk, Kp, M, N, Kd);
    gemm_nt_bias<<<gemm_grid, 256>>>(value, Wv, bv, Vp, M, N, Kd);

    // fused scores -> streaming top-k -> softmax -> scatter -> attn
    size_t smem = (size_t)(3 * 64 * 68) * sizeof(float);   // 52224 B
    cudaFuncSetAttribute(attn_topk_kernel,
                         cudaFuncAttributeMaxDynamicSharedMemorySize, (int)smem);
    dim3 attn_grid(S_ / 64, H_, B_);      // (32, 16, 2)
    attn_topk_kernel<<<attn_grid, 256, smem>>>(Qp, Kp, Vp, weights, Ap);

    // output projection
    gemm_nt_bias<<<gemm_grid, 256>>>(Ap, Wo, bo, out, M, N, Kd);
}